// round 13
// baseline (speedup 1.0000x reference)
#include <cuda_runtime.h>
#include <cuda_fp16.h>
#include <cstdint>

#define DD   1024
#define SS   1024
#define TT   16
#define PP   256
#define BB   8
#define BT   128
#define MROWS 32768

// ---------------- device scratch ----------------
__device__ __half g_WoutRh[DD*SS];
__device__ __half g_BmRh [SS*SS];
__device__ __half g_ARh  [SS*SS];
__device__ __half g_WinTRh[DD*SS];
__device__ __half g_BmTh [SS*SS];
__device__ __half g_Hth  [DD*SS];
__device__ __half g_Gth  [DD*SS];
__device__ __half g_MqTh [SS*DD];
__device__ __half g_MwTh [DD*DD];
__device__ __half g_Xsumh[(size_t)MROWS*DD];
__device__ __half g_xbarh[BT*DD];
__device__ __half g_statesh[BT*SS];
__device__ float g_xbarp[8*BT*DD];
__device__ float g_qp  [4*BT*SS];
__device__ float g_rp  [4*BT*DD];
__device__ float g_q   [BT*SS];
__device__ float g_states[BT*SS];
__device__ float g_r   [BT*DD];
__device__ float g_c   [DD];
__device__ float g_bq  [SS];
__device__ unsigned g_barcnt;

// ---------------- helpers ----------------
__device__ __forceinline__ uint32_t smem_u32(const void* p) {
    uint32_t a;
    asm("{ .reg .u64 t; cvta.to.shared.u64 t, %1; cvt.u32.u64 %0, t; }" : "=r"(a) : "l"(p));
    return a;
}
__device__ __forceinline__ void cp_async16(uint32_t dst, const void* src) {
    asm volatile("cp.async.cg.shared.global [%0], [%1], 16;" :: "r"(dst), "l"(src) : "memory");
}
#define CP_COMMIT() asm volatile("cp.async.commit_group;" ::: "memory")
#define CP_WAIT1()  asm volatile("cp.async.wait_group 1;" ::: "memory")

__device__ __forceinline__ void ldsm_x4(uint32_t* r, uint32_t addr) {
    asm volatile("ldmatrix.sync.aligned.m8n8.x4.shared.b16 {%0,%1,%2,%3}, [%4];"
        : "=r"(r[0]), "=r"(r[1]), "=r"(r[2]), "=r"(r[3]) : "r"(addr));
}
__device__ __forceinline__ void mma_f16(float* d, const uint32_t* a, const uint32_t* b) {
    asm volatile(
        "mma.sync.aligned.m16n8k16.row.col.f32.f16.f16.f32 "
        "{%0,%1,%2,%3}, {%4,%5,%6,%7}, {%8,%9}, {%0,%1,%2,%3};"
        : "+f"(d[0]), "+f"(d[1]), "+f"(d[2]), "+f"(d[3])
        : "r"(a[0]), "r"(a[1]), "r"(a[2]), "r"(a[3]), "r"(b[0]), "r"(b[1]));
}

// ================= fp16 NT GEMM (as in R11/R12; simple compute body) =================
#define OPA_B   18432u
#define STAGE_B 36864u
#define GEMM_SM (3 * 36864)

template <int EPI, int KSPLIT>
__global__ void __launch_bounds__(128, 2) f16g(
    const __half* __restrict__ A0, const __half* __restrict__ A1, const __half* __restrict__ A2,
    const __half* __restrict__ B0, const __half* __restrict__ B1, const __half* __restrict__ B2,
    void* __restrict__ C0, void* __restrict__ C1, void* __restrict__ C2)
{
    constexpr int CH = 16 / KSPLIT;

    extern __shared__ char smem[];
    const uint32_t sb = smem_u32(smem);

    const int tid  = threadIdx.x;
    const int lane = tid & 31;
    const int w    = tid >> 5;
    const int wm   = (w >> 1) * 64;
    const int wn   = (w & 1) * 64;
    const int g    = lane >> 2;
    const int tg   = lane & 3;

    const int zm = blockIdx.z / KSPLIT;
    const int ks = blockIdx.z % KSPLIT;
    const __half* __restrict__ Asel = zm == 0 ? A0 : (zm == 1 ? A1 : A2);
    const __half* __restrict__ Bsel = zm == 0 ? B0 : (zm == 1 ? B1 : B2);
    void* __restrict__ Csel         = zm == 0 ? C0 : (zm == 1 ? C1 : C2);

    const int rowBase = blockIdx.y * 128;
    const int colBase = blockIdx.x * 128;
    const __half* __restrict__ Ag = Asel + (size_t)rowBase * 1024;
    const __half* __restrict__ Bg = Bsel + (size_t)colBase * 1024;
    const int Mrows = gridDim.y * 128;

    float acc[4][8][4];
#pragma unroll
    for (int i = 0; i < 4; i++)
#pragma unroll
        for (int j = 0; j < 8; j++)
#pragma unroll
            for (int k = 0; k < 4; k++) acc[i][j][k] = 0.f;

    auto load_stage = [&](int chunk, int st) {
        const uint32_t dA = sb + st * STAGE_B;
        const uint32_t dB = dA + OPA_B;
        const int k0 = chunk * 64;
#pragma unroll
        for (int i = 0; i < 8; i++) {
            int idx = i * 128 + tid;
            int r = idx >> 3, c = idx & 7;
            cp_async16(dA + r * 144 + c * 16, Ag + (size_t)r * 1024 + k0 + c * 8);
        }
#pragma unroll
        for (int i = 0; i < 8; i++) {
            int idx = i * 128 + tid;
            int r = idx >> 3, c = idx & 7;
            cp_async16(dB + r * 144 + c * 16, Bg + (size_t)r * 1024 + k0 + c * 8);
        }
        CP_COMMIT();
    };

    const uint32_t aoff = (uint32_t)((wm + (lane & 15)) * 144 + ((lane >> 4) << 4));
    const uint32_t boff = (uint32_t)((wn + ((lane >> 4) << 3) + (lane & 7)) * 144 +
                                     (((lane >> 3) & 1) << 4));

    auto compute = [&](int st) {
        const uint32_t ab = sb + st * STAGE_B + aoff;
        const uint32_t bb = sb + st * STAGE_B + OPA_B + boff;
#pragma unroll
        for (int kk = 0; kk < 4; kk++) {
            const uint32_t kb = kk * 32;
            uint32_t a[4][4], bq[4][4];
#pragma unroll
            for (int mi = 0; mi < 4; mi++) ldsm_x4(a[mi], ab + mi * 2304 + kb);
#pragma unroll
            for (int nj = 0; nj < 4; nj++) ldsm_x4(bq[nj], bb + nj * 2304 + kb);
#pragma unroll
            for (int mi = 0; mi < 4; mi++)
#pragma unroll
                for (int ni = 0; ni < 8; ni++)
                    mma_f16(acc[mi][ni], a[mi], &bq[ni >> 1][(ni & 1) * 2]);
        }
    };

    load_stage(ks * CH + 0, 0);
    load_stage(ks * CH + 1, 1);

    int st = 0;
#pragma unroll 1
    for (int c = 0; c < CH; c++) {
        CP_WAIT1();
        __syncthreads();
        if (c + 2 < CH) {
            int nst = st + 2; if (nst >= 3) nst -= 3;
            load_stage(ks * CH + c + 2, nst);
        } else {
            CP_COMMIT();
        }
        compute(st);
        if (++st == 3) st = 0;
    }

#pragma unroll
    for (int mi = 0; mi < 4; mi++) {
        const int row0 = rowBase + wm + mi * 16 + g;
        const int row1 = row0 + 8;
#pragma unroll
        for (int ni = 0; ni < 8; ni++) {
            const int col = colBase + wn + ni * 8 + tg * 2;
            float v0 = acc[mi][ni][0], v1 = acc[mi][ni][1];
            float v2 = acc[mi][ni][2], v3 = acc[mi][ni][3];
            if (EPI == 2) {
                float2 ra = *(const float2*)(g_r + (size_t)(row0 >> 8) * 1024 + col);
                float2 rb = *(const float2*)(g_r + (size_t)(row1 >> 8) * 1024 + col);
                float2 cc = *(const float2*)(g_c + col);
                *(float2*)((float*)Csel + (size_t)row0 * 1024 + col) =
                    make_float2(v0 + ra.x + cc.x, v1 + ra.y + cc.y);
                *(float2*)((float*)Csel + (size_t)row1 * 1024 + col) =
                    make_float2(v2 + rb.x + cc.x, v3 + rb.y + cc.y);
            } else if (EPI == 1) {
                float* Cf = (float*)Csel + (size_t)ks * Mrows * 1024;
                *(float2*)(Cf + (size_t)row0 * 1024 + col) = make_float2(v0, v1);
                *(float2*)(Cf + (size_t)row1 * 1024 + col) = make_float2(v2, v3);
            } else {
                *(__half2*)((__half*)Csel + (size_t)row0 * 1024 + col) =
                    __floats2half2_rn(v0, v1);
                *(__half2*)((__half*)Csel + (size_t)row1 * 1024 + col) =
                    __floats2half2_rn(v2, v3);
            }
        }
    }
}

// ---------------- prepass (p-split 8): Xsumh + partial xbar sums ----------------
__global__ void prepass_k(const float* __restrict__ x, const float* __restrict__ pos) {
    const int bt = blockIdx.y;
    const int t  = bt & 15;
    const int z  = blockIdx.z;                   // 0..7, 32 p-rows each
    const int d  = (blockIdx.x * 256 + threadIdx.x) * 2;
    const int p0 = z * 32;
    const float* xp = x   + ((size_t)bt * PP + p0) * DD + d;
    const float* pp = pos + ((size_t)t  * PP + p0) * DD + d;
    __half* op = g_Xsumh + ((size_t)bt * PP + p0) * DD + d;
    float sx = 0.f, sy = 0.f;
#pragma unroll 8
    for (int p = 0; p < 32; p++) {
        float2 a = *(const float2*)(xp + (size_t)p * DD);
        float2 b = *(const float2*)(pp + (size_t)p * DD);
        float vx = a.x + b.x, vy = a.y + b.y;
        sx += vx; sy += vy;
        *(__half2*)(op + (size_t)p * DD) = __floats2half2_rn(vx, vy);
    }
    float* xb = g_xbarp + ((size_t)z * BT + bt) * DD + d;
    xb[0] = sx; xb[1] = sy;
}

// ---------------- xbar reduce (8 partials) ----------------
__global__ void xred_k() {
    const int bt = blockIdx.y;
    const int d  = (blockIdx.x * 256 + threadIdx.x) * 2;
    float sx = 0.f, sy = 0.f;
#pragma unroll
    for (int z = 0; z < 8; z++) {
        const float* xb = g_xbarp + ((size_t)z * BT + bt) * DD + d;
        sx += xb[0]; sy += xb[1];
    }
    *(__half2*)(g_xbarh + (size_t)bt * DD + d) =
        __floats2half2_rn(sx * (1.0f / PP), sy * (1.0f / PP));
}

// ---------------- merged weight prep ----------------
__global__ void wprep_k(const float* __restrict__ W_in, const float* __restrict__ Bm,
                        const float* __restrict__ W_out, const float* __restrict__ Amat) {
    const int z = blockIdx.z;
    if (z < 2) {
        __shared__ float tile[32][33];
        const float* in = z ? Bm : W_in;
        __half* out = z ? g_BmTh : g_WinTRh;
        int x = blockIdx.x * 32 + threadIdx.x;
        int y = blockIdx.y * 32 + threadIdx.y;
#pragma unroll
        for (int i = 0; i < 32; i += 8)
            tile[threadIdx.y + i][threadIdx.x] = in[(size_t)(y + i) * DD + x];
        __syncthreads();
        x = blockIdx.y * 32 + threadIdx.x;
        y = blockIdx.x * 32 + threadIdx.y;
#pragma unroll
        for (int i = 0; i < 32; i += 8)
            out[(size_t)(y + i) * DD + x] =
                __float2half_rn(tile[threadIdx.x][threadIdx.y + i]);
    } else {
        const float* in = z == 2 ? W_out : (z == 3 ? Bm : Amat);
        __half* out = z == 2 ? g_WoutRh : (z == 3 ? g_BmRh : g_ARh);
        int x = blockIdx.x * 32 + threadIdx.x;
        int y = blockIdx.y * 32 + threadIdx.y;
#pragma unroll
        for (int i = 0; i < 32; i += 8)
            out[(size_t)(y + i) * DD + x] = __float2half_rn(in[(size_t)(y + i) * DD + x]);
    }
}

// ---------------- bq[d] = BmTh[d]·b_in ----------------
__global__ void bq_k(const float* __restrict__ b_in) {
    __shared__ float red[256];
    const int d = blockIdx.x;
    const int tid = threadIdx.x;
    const __half* row = g_BmTh + (size_t)d * 1024;
    float s = 0.f;
    for (int j = tid; j < SS; j += 256) s += __half2float(row[j]) * b_in[j];
    red[tid] = s;
    __syncthreads();
    for (int o = 128; o > 0; o >>= 1) {
        if (tid < o) red[tid] += red[tid + o];
        __syncthreads();
    }
    if (tid == 0) g_bq[d] = red[0];
}

// ---------------- c[d] = Hth[d]·b_in + b_out[d] ----------------
__global__ void cvec_k(const float* __restrict__ b_in, const float* __restrict__ b_out) {
    __shared__ float red[256];
    const int d = blockIdx.x;
    const int tid = threadIdx.x;
    const __half* row = g_Hth + (size_t)d * 1024;
    float s = 0.f;
    for (int j = tid; j < SS; j += 256) s += __half2float(row[j]) * b_in[j];
    red[tid] = s;
    __syncthreads();
    for (int o = 128; o > 0; o >>= 1) {
        if (tid < o) red[tid] += red[tid + o];
        __syncthreads();
    }
    if (tid == 0) g_c[d] = red[0] + b_out[d];
}

// ---------------- sum 4 split-K partials ----------------
__global__ void sum4_k(const float* __restrict__ in, const float* __restrict__ addv,
                       float* __restrict__ out) {
    const int n = BT * 1024;
    int i = (blockIdx.x * 256 + threadIdx.x) * 4;
    float4 a = *(const float4*)(in + i);
    float4 b = *(const float4*)(in + n + i);
    float4 c = *(const float4*)(in + 2 * n + i);
    float4 d = *(const float4*)(in + 3 * n + i);
    float4 o;
    o.x = a.x + b.x + c.x + d.x; o.y = a.y + b.y + c.y + d.y;
    o.z = a.z + b.z + c.z + d.z; o.w = a.w + b.w + c.w + d.w;
    if (addv) {
        int col = i & 1023;
        float4 av = *(const float4*)(addv + col);
        o.x += av.x; o.y += av.y; o.z += av.z; o.w += av.w;
    }
    *(float4*)(out + i) = o;
}

// ---------------- scan: init + fused 15-step kernel with sw grid barrier ----------------
__global__ void scan_init_k(const float* __restrict__ init) {
    if (blockIdx.x == 0 && threadIdx.x == 0) g_barcnt = 0u;
    int s = blockIdx.x * 256 + threadIdx.x;
    float v = init[s];
#pragma unroll
    for (int b = 0; b < BB; b++) {
        g_states[(size_t)(b * 16) * SS + s] = v;
        g_statesh[(size_t)(b * 16) * SS + s] = __float2half_rn(v);
    }
}

// 64 CTAs (always co-resident), 15 steps, software grid barrier between steps.
__global__ void __launch_bounds__(256) scan_fused_k(const float* __restrict__ Amat) {
    __shared__ float st[BB][SS];
    __shared__ float red[BB][256];
    const int tid  = threadIdx.x;
    const int col  = blockIdx.x * 16 + (tid & 15);
    const int part = tid >> 4;
    const int k0   = part * 64;

#pragma unroll 1
    for (int t = 0; t < 15; t++) {
        // load current states (L2-coherent loads; L1 may hold stale lines across steps)
        for (int i = tid; i < BB * SS; i += 256) {
            int b = i >> 10, s = i & 1023;
            st[b][s] = __ldcg(&g_states[(size_t)(b * 16 + t) * SS + s]);
        }
        __syncthreads();
        float acc[BB] = {};
#pragma unroll 4
        for (int k = k0; k < k0 + 64; k++) {
            float av = Amat[(size_t)k * SS + col];
#pragma unroll
            for (int b = 0; b < BB; b++) acc[b] += st[b][k] * av;
        }
#pragma unroll
        for (int b = 0; b < BB; b++) red[b][tid] = acc[b];
        __syncthreads();
        for (int o = 8; o > 0; o >>= 1) {
            if (part < o) {
#pragma unroll
                for (int b = 0; b < BB; b++) red[b][tid] += red[b][tid + (o << 4)];
            }
            __syncthreads();
        }
        if (part == 0) {
#pragma unroll
            for (int b = 0; b < BB; b++) {
                float v = red[b][tid] + g_q[(size_t)(b * 16 + t) * SS + col];
                g_states[(size_t)(b * 16 + t + 1) * SS + col] = v;
                g_statesh[(size_t)(b * 16 + t + 1) * SS + col] = __float2half_rn(v);
            }
        }
        // ---- software grid barrier ----
        __threadfence();            // publish this CTA's state writes
        __syncthreads();            // all threads (incl. writers) fenced
        if (tid == 0) {
            atomicAdd(&g_barcnt, 1u);
            const unsigned target = (unsigned)((t + 1) * gridDim.x);
            while (atomicAdd(&g_barcnt, 0u) < target) {}
        }
        __syncthreads();
    }
}

// ---------------- host ----------------
extern "C" void kernel_launch(void* const* d_in, const int* in_sizes, int n_in,
                              void* d_out, int out_size) {
    const float* x     = (const float*)d_in[0];
    const float* pos   = (const float*)d_in[1];
    const float* W_in  = (const float*)d_in[2];
    const float* b_in  = (const float*)d_in[3];
    const float* W_out = (const float*)d_in[4];
    const float* b_out = (const float*)d_in[5];
    const float* Amat  = (const float*)d_in[6];
    const float* Bm    = (const float*)d_in[7];
    const float* init  = (const float*)d_in[8];
    float* out = (float*)d_out;

    __half *WoutRh, *BmRh, *ARh, *WinTRh, *BmTh, *Hth, *Gth, *MqTh, *MwTh, *Xsumh, *xbarh, *statesh;
    float *qp, *rp, *q, *r, *bqv;
    cudaGetSymbolAddress((void**)&WoutRh, g_WoutRh);
    cudaGetSymbolAddress((void**)&BmRh,   g_BmRh);
    cudaGetSymbolAddress((void**)&ARh,    g_ARh);
    cudaGetSymbolAddress((void**)&WinTRh, g_WinTRh);
    cudaGetSymbolAddress((void**)&BmTh,   g_BmTh);
    cudaGetSymbolAddress((void**)&Hth,    g_Hth);
    cudaGetSymbolAddress((void**)&Gth,    g_Gth);
    cudaGetSymbolAddress((void**)&MqTh,   g_MqTh);
    cudaGetSymbolAddress((void**)&MwTh,   g_MwTh);
    cudaGetSymbolAddress((void**)&Xsumh,  g_Xsumh);
    cudaGetSymbolAddress((void**)&xbarh,  g_xbarh);
    cudaGetSymbolAddress((void**)&statesh,g_statesh);
    cudaGetSymbolAddress((void**)&qp,     g_qp);
    cudaGetSymbolAddress((void**)&rp,     g_rp);
    cudaGetSymbolAddress((void**)&q,      g_q);
    cudaGetSymbolAddress((void**)&r,      g_r);
    cudaGetSymbolAddress((void**)&bqv,    g_bq);

    static bool s_init = false;
    static cudaStream_t s2 = 0;
    static cudaEvent_t e0, eB, eG, eW;
    if (!s_init) {
        if (cudaStreamCreateWithFlags(&s2, cudaStreamNonBlocking) != cudaSuccess) s2 = 0;
        cudaEventCreateWithFlags(&e0, cudaEventDisableTiming);
        cudaEventCreateWithFlags(&eB, cudaEventDisableTiming);
        cudaEventCreateWithFlags(&eG, cudaEventDisableTiming);
        cudaEventCreateWithFlags(&eW, cudaEventDisableTiming);
        cudaFuncSetAttribute((const void*)f16g<0, 1>,
                             cudaFuncAttributeMaxDynamicSharedMemorySize, GEMM_SM);
        cudaFuncSetAttribute((const void*)f16g<1, 4>,
                             cudaFuncAttributeMaxDynamicSharedMemorySize, GEMM_SM);
        cudaFuncSetAttribute((const void*)f16g<2, 1>,
                             cudaFuncAttributeMaxDynamicSharedMemorySize, GEMM_SM);
        s_init = true;
    }

    // ---- fork ----
    cudaEventRecord(e0, 0);

    // s2: weight prep -> bq -> MqTh (eB) -> Ht/Gt (eG) -> MwTh + c (eW)
    cudaStreamWaitEvent(s2, e0, 0);
    wprep_k<<<dim3(32, 32, 5), dim3(32, 8), 0, s2>>>(W_in, Bm, W_out, Amat);
    bq_k<<<1024, 256, 0, s2>>>(b_in);
    f16g<0, 1><<<dim3(8, 8, 1), 128, GEMM_SM, s2>>>(
        BmTh, nullptr, nullptr, WinTRh, nullptr, nullptr, MqTh, nullptr, nullptr);
    cudaEventRecord(eB, s2);
    f16g<0, 1><<<dim3(8, 8, 2), 128, GEMM_SM, s2>>>(
        WoutRh, WoutRh, nullptr, BmRh, ARh, nullptr, Hth, Gth, nullptr);
    cudaEventRecord(eG, s2);
    f16g<0, 1><<<dim3(8, 8, 1), 128, GEMM_SM, s2>>>(
        Hth, nullptr, nullptr, WinTRh, nullptr, nullptr, MwTh, nullptr, nullptr);
    cvec_k<<<1024, 256, 0, s2>>>(b_in, b_out);
    cudaEventRecord(eW, s2);

    // default stream: prepass -> xred -> q -> scan -> r -> main
    prepass_k<<<dim3(2, BT, 8), 256>>>(x, pos);
    xred_k<<<dim3(2, BT), 256>>>();
    cudaStreamWaitEvent(0, eB, 0);
    f16g<1, 4><<<dim3(8, 1, 4), 128, GEMM_SM>>>(
        xbarh, nullptr, nullptr, MqTh, nullptr, nullptr, qp, nullptr, nullptr);
    sum4_k<<<128, 256>>>(qp, bqv, q);
    scan_init_k<<<4, 256>>>(init);
    scan_fused_k<<<64, 256>>>(Amat);
    cudaStreamWaitEvent(0, eG, 0);
    f16g<1, 4><<<dim3(8, 1, 4), 128, GEMM_SM>>>(
        statesh, nullptr, nullptr, Gth, nullptr, nullptr, rp, nullptr, nullptr);
    sum4_k<<<128, 256>>>(rp, nullptr, r);

    // main GEMM fused with r+c epilogue
    cudaStreamWaitEvent(0, eW, 0);
    f16g<2, 1><<<dim3(8, 256, 1), 128, GEMM_SM>>>(
        Xsumh, nullptr, nullptr, MwTh, nullptr, nullptr, out, nullptr, nullptr);
}

// round 14
// speedup vs baseline: 1.0158x; 1.0158x over previous
#include <cuda_runtime.h>
#include <cuda_fp16.h>
#include <cstdint>

#define DD   1024
#define SS   1024
#define TT   16
#define PP   256
#define BB   8
#define BT   128
#define MROWS 32768

// ---------------- device scratch ----------------
__device__ __half g_WoutRh[DD*SS];
__device__ __half g_BmRh [SS*SS];
__device__ __half g_ARh  [SS*SS];
__device__ __half g_WinTRh[DD*SS];
__device__ __half g_BmTh [SS*SS];
__device__ __half g_Hth  [DD*SS];
__device__ __half g_Gth  [DD*SS];
__device__ __half g_MqTh [SS*DD];
__device__ __half g_MwTh [DD*DD];
__device__ __half g_Xsumh[(size_t)MROWS*DD];
__device__ __half g_xbarh[BT*DD];
__device__ __half g_statesh[BT*SS];
__device__ float g_xbarp[8*BT*DD];
__device__ float g_qp  [4*BT*SS];
__device__ float g_rp  [4*BT*DD];
__device__ float g_q   [BT*SS];
__device__ float g_states[BT*SS];
__device__ float g_r   [BT*DD];
__device__ float g_c   [DD];
__device__ float g_bq  [SS];
__device__ unsigned g_barcnt;

// ---------------- helpers ----------------
__device__ __forceinline__ uint32_t smem_u32(const void* p) {
    uint32_t a;
    asm("{ .reg .u64 t; cvta.to.shared.u64 t, %1; cvt.u32.u64 %0, t; }" : "=r"(a) : "l"(p));
    return a;
}
__device__ __forceinline__ void cp_async16(uint32_t dst, const void* src) {
    asm volatile("cp.async.cg.shared.global [%0], [%1], 16;" :: "r"(dst), "l"(src) : "memory");
}
#define CP_COMMIT() asm volatile("cp.async.commit_group;" ::: "memory")
#define CP_WAIT1()  asm volatile("cp.async.wait_group 1;" ::: "memory")

__device__ __forceinline__ void ldsm_x4(uint32_t* r, uint32_t addr) {
    asm volatile("ldmatrix.sync.aligned.m8n8.x4.shared.b16 {%0,%1,%2,%3}, [%4];"
        : "=r"(r[0]), "=r"(r[1]), "=r"(r[2]), "=r"(r[3]) : "r"(addr));
}
__device__ __forceinline__ void mma_f16(float* d, const uint32_t* a, const uint32_t* b) {
    asm volatile(
        "mma.sync.aligned.m16n8k16.row.col.f32.f16.f16.f32 "
        "{%0,%1,%2,%3}, {%4,%5,%6,%7}, {%8,%9}, {%0,%1,%2,%3};"
        : "+f"(d[0]), "+f"(d[1]), "+f"(d[2]), "+f"(d[3])
        : "r"(a[0]), "r"(a[1]), "r"(a[2]), "r"(a[3]), "r"(b[0]), "r"(b[1]));
}

// ================= fp16 NT GEMM (proven R11/R12 config) =================
#define OPA_B   18432u
#define STAGE_B 36864u
#define GEMM_SM (3 * 36864)

template <int EPI, int KSPLIT>
__global__ void __launch_bounds__(128, 2) f16g(
    const __half* __restrict__ A0, const __half* __restrict__ A1, const __half* __restrict__ A2,
    const __half* __restrict__ B0, const __half* __restrict__ B1, const __half* __restrict__ B2,
    void* __restrict__ C0, void* __restrict__ C1, void* __restrict__ C2)
{
    constexpr int CH = 16 / KSPLIT;

    extern __shared__ char smem[];
    const uint32_t sb = smem_u32(smem);

    const int tid  = threadIdx.x;
    const int lane = tid & 31;
    const int w    = tid >> 5;
    const int wm   = (w >> 1) * 64;
    const int wn   = (w & 1) * 64;
    const int g    = lane >> 2;
    const int tg   = lane & 3;

    const int zm = blockIdx.z / KSPLIT;
    const int ks = blockIdx.z % KSPLIT;
    const __half* __restrict__ Asel = zm == 0 ? A0 : (zm == 1 ? A1 : A2);
    const __half* __restrict__ Bsel = zm == 0 ? B0 : (zm == 1 ? B1 : B2);
    void* __restrict__ Csel         = zm == 0 ? C0 : (zm == 1 ? C1 : C2);

    const int rowBase = blockIdx.y * 128;
    const int colBase = blockIdx.x * 128;
    const __half* __restrict__ Ag = Asel + (size_t)rowBase * 1024;
    const __half* __restrict__ Bg = Bsel + (size_t)colBase * 1024;
    const int Mrows = gridDim.y * 128;

    float acc[4][8][4];
#pragma unroll
    for (int i = 0; i < 4; i++)
#pragma unroll
        for (int j = 0; j < 8; j++)
#pragma unroll
            for (int k = 0; k < 4; k++) acc[i][j][k] = 0.f;

    auto load_stage = [&](int chunk, int st) {
        const uint32_t dA = sb + st * STAGE_B;
        const uint32_t dB = dA + OPA_B;
        const int k0 = chunk * 64;
#pragma unroll
        for (int i = 0; i < 8; i++) {
            int idx = i * 128 + tid;
            int r = idx >> 3, c = idx & 7;
            cp_async16(dA + r * 144 + c * 16, Ag + (size_t)r * 1024 + k0 + c * 8);
        }
#pragma unroll
        for (int i = 0; i < 8; i++) {
            int idx = i * 128 + tid;
            int r = idx >> 3, c = idx & 7;
            cp_async16(dB + r * 144 + c * 16, Bg + (size_t)r * 1024 + k0 + c * 8);
        }
        CP_COMMIT();
    };

    const uint32_t aoff = (uint32_t)((wm + (lane & 15)) * 144 + ((lane >> 4) << 4));
    const uint32_t boff = (uint32_t)((wn + ((lane >> 4) << 3) + (lane & 7)) * 144 +
                                     (((lane >> 3) & 1) << 4));

    auto compute = [&](int st) {
        const uint32_t ab = sb + st * STAGE_B + aoff;
        const uint32_t bb = sb + st * STAGE_B + OPA_B + boff;
#pragma unroll
        for (int kk = 0; kk < 4; kk++) {
            const uint32_t kb = kk * 32;
            uint32_t a[4][4], bq[4][4];
#pragma unroll
            for (int mi = 0; mi < 4; mi++) ldsm_x4(a[mi], ab + mi * 2304 + kb);
#pragma unroll
            for (int nj = 0; nj < 4; nj++) ldsm_x4(bq[nj], bb + nj * 2304 + kb);
#pragma unroll
            for (int mi = 0; mi < 4; mi++)
#pragma unroll
                for (int ni = 0; ni < 8; ni++)
                    mma_f16(acc[mi][ni], a[mi], &bq[ni >> 1][(ni & 1) * 2]);
        }
    };

    load_stage(ks * CH + 0, 0);
    load_stage(ks * CH + 1, 1);

    int st = 0;
#pragma unroll 1
    for (int c = 0; c < CH; c++) {
        CP_WAIT1();
        __syncthreads();
        if (c + 2 < CH) {
            int nst = st + 2; if (nst >= 3) nst -= 3;
            load_stage(ks * CH + c + 2, nst);
        } else {
            CP_COMMIT();
        }
        compute(st);
        if (++st == 3) st = 0;
    }

#pragma unroll
    for (int mi = 0; mi < 4; mi++) {
        const int row0 = rowBase + wm + mi * 16 + g;
        const int row1 = row0 + 8;
#pragma unroll
        for (int ni = 0; ni < 8; ni++) {
            const int col = colBase + wn + ni * 8 + tg * 2;
            float v0 = acc[mi][ni][0], v1 = acc[mi][ni][1];
            float v2 = acc[mi][ni][2], v3 = acc[mi][ni][3];
            if (EPI == 2) {
                float2 ra = *(const float2*)(g_r + (size_t)(row0 >> 8) * 1024 + col);
                float2 rb = *(const float2*)(g_r + (size_t)(row1 >> 8) * 1024 + col);
                float2 cc = *(const float2*)(g_c + col);
                *(float2*)((float*)Csel + (size_t)row0 * 1024 + col) =
                    make_float2(v0 + ra.x + cc.x, v1 + ra.y + cc.y);
                *(float2*)((float*)Csel + (size_t)row1 * 1024 + col) =
                    make_float2(v2 + rb.x + cc.x, v3 + rb.y + cc.y);
            } else if (EPI == 1) {
                float* Cf = (float*)Csel + (size_t)ks * Mrows * 1024;
                *(float2*)(Cf + (size_t)row0 * 1024 + col) = make_float2(v0, v1);
                *(float2*)(Cf + (size_t)row1 * 1024 + col) = make_float2(v2, v3);
            } else {
                *(__half2*)((__half*)Csel + (size_t)row0 * 1024 + col) =
                    __floats2half2_rn(v0, v1);
                *(__half2*)((__half*)Csel + (size_t)row1 * 1024 + col) =
                    __floats2half2_rn(v2, v3);
            }
        }
    }
}

// ---------------- prepass (p-split 8, float4): Xsumh + partial xbar sums ----------------
__global__ void __launch_bounds__(256) prepass_k(const float* __restrict__ x,
                                                 const float* __restrict__ pos) {
    const int bt = blockIdx.y;
    const int t  = bt & 15;
    const int z  = blockIdx.z;                   // 0..7, 32 p-rows each
    const int d  = threadIdx.x * 4;
    const int p0 = z * 32;
    const float* xp = x   + ((size_t)bt * PP + p0) * DD + d;
    const float* pp = pos + ((size_t)t  * PP + p0) * DD + d;
    __half* op = g_Xsumh + ((size_t)bt * PP + p0) * DD + d;
    float s0 = 0.f, s1 = 0.f, s2 = 0.f, s3 = 0.f;
#pragma unroll 4
    for (int p = 0; p < 32; p++) {
        float4 a = *(const float4*)(xp + (size_t)p * DD);
        float4 b = *(const float4*)(pp + (size_t)p * DD);
        float v0 = a.x + b.x, v1 = a.y + b.y, v2 = a.z + b.z, v3 = a.w + b.w;
        s0 += v0; s1 += v1; s2 += v2; s3 += v3;
        __half2 h0 = __floats2half2_rn(v0, v1);
        __half2 h1 = __floats2half2_rn(v2, v3);
        uint2 pk = make_uint2(*(uint32_t*)&h0, *(uint32_t*)&h1);
        *(uint2*)(op + (size_t)p * DD) = pk;
    }
    *(float4*)(g_xbarp + ((size_t)z * BT + bt) * DD + d) = make_float4(s0, s1, s2, s3);
}

// ---------------- xbar reduce (8 partials, float4) ----------------
__global__ void __launch_bounds__(256) xred_k() {
    const int bt = blockIdx.y;
    const int d  = threadIdx.x * 4;
    float s0 = 0.f, s1 = 0.f, s2 = 0.f, s3 = 0.f;
#pragma unroll
    for (int z = 0; z < 8; z++) {
        float4 v = *(const float4*)(g_xbarp + ((size_t)z * BT + bt) * DD + d);
        s0 += v.x; s1 += v.y; s2 += v.z; s3 += v.w;
    }
    __half2 h0 = __floats2half2_rn(s0 * (1.0f / PP), s1 * (1.0f / PP));
    __half2 h1 = __floats2half2_rn(s2 * (1.0f / PP), s3 * (1.0f / PP));
    *(uint2*)(g_xbarh + (size_t)bt * DD + d) = make_uint2(*(uint32_t*)&h0, *(uint32_t*)&h1);
}

// ---------------- merged weight prep ----------------
__global__ void wprep_k(const float* __restrict__ W_in, const float* __restrict__ Bm,
                        const float* __restrict__ W_out, const float* __restrict__ Amat) {
    const int z = blockIdx.z;
    if (z < 2) {
        __shared__ float tile[32][33];
        const float* in = z ? Bm : W_in;
        __half* out = z ? g_BmTh : g_WinTRh;
        int x = blockIdx.x * 32 + threadIdx.x;
        int y = blockIdx.y * 32 + threadIdx.y;
#pragma unroll
        for (int i = 0; i < 32; i += 8)
            tile[threadIdx.y + i][threadIdx.x] = in[(size_t)(y + i) * DD + x];
        __syncthreads();
        x = blockIdx.y * 32 + threadIdx.x;
        y = blockIdx.x * 32 + threadIdx.y;
#pragma unroll
        for (int i = 0; i < 32; i += 8)
            out[(size_t)(y + i) * DD + x] =
                __float2half_rn(tile[threadIdx.x][threadIdx.y + i]);
    } else {
        const float* in = z == 2 ? W_out : (z == 3 ? Bm : Amat);
        __half* out = z == 2 ? g_WoutRh : (z == 3 ? g_BmRh : g_ARh);
        int x = blockIdx.x * 32 + threadIdx.x;
        int y = blockIdx.y * 32 + threadIdx.y;
#pragma unroll
        for (int i = 0; i < 32; i += 8)
            out[(size_t)(y + i) * DD + x] = __float2half_rn(in[(size_t)(y + i) * DD + x]);
    }
}

// ---------------- bq[d] = BmTh[d]·b_in ----------------
__global__ void bq_k(const float* __restrict__ b_in) {
    __shared__ float red[256];
    const int d = blockIdx.x;
    const int tid = threadIdx.x;
    const __half* row = g_BmTh + (size_t)d * 1024;
    float s = 0.f;
    for (int j = tid; j < SS; j += 256) s += __half2float(row[j]) * b_in[j];
    red[tid] = s;
    __syncthreads();
    for (int o = 128; o > 0; o >>= 1) {
        if (tid < o) red[tid] += red[tid + o];
        __syncthreads();
    }
    if (tid == 0) g_bq[d] = red[0];
}

// ---------------- c[d] = Hth[d]·b_in + b_out[d] ----------------
__global__ void cvec_k(const float* __restrict__ b_in, const float* __restrict__ b_out) {
    __shared__ float red[256];
    const int d = blockIdx.x;
    const int tid = threadIdx.x;
    const __half* row = g_Hth + (size_t)d * 1024;
    float s = 0.f;
    for (int j = tid; j < SS; j += 256) s += __half2float(row[j]) * b_in[j];
    red[tid] = s;
    __syncthreads();
    for (int o = 128; o > 0; o >>= 1) {
        if (tid < o) red[tid] += red[tid + o];
        __syncthreads();
    }
    if (tid == 0) g_c[d] = red[0] + b_out[d];
}

// ---------------- q finalize + scan init (merged) ----------------
__global__ void qinit_k(const float* __restrict__ init) {
    const int n = BT * 1024;
    int i = (blockIdx.x * 256 + threadIdx.x) * 4;     // 128 CTAs cover BT*SS
    float4 a = *(const float4*)(g_qp + i);
    float4 b = *(const float4*)(g_qp + n + i);
    float4 c = *(const float4*)(g_qp + 2 * n + i);
    float4 d4 = *(const float4*)(g_qp + 3 * n + i);
    int col = i & 1023;
    float4 av = *(const float4*)(g_bq + col);
    float4 o;
    o.x = a.x + b.x + c.x + d4.x + av.x;
    o.y = a.y + b.y + c.y + d4.y + av.y;
    o.z = a.z + b.z + c.z + d4.z + av.z;
    o.w = a.w + b.w + c.w + d4.w + av.w;
    *(float4*)(g_q + i) = o;

    if (blockIdx.x == 0 && threadIdx.x == 0) g_barcnt = 0u;
    if (blockIdx.x < 4) {
        int s = blockIdx.x * 256 + threadIdx.x;
        float v = init[s];
#pragma unroll
        for (int b2 = 0; b2 < BB; b2++) {
            g_states[(size_t)(b2 * 16) * SS + s] = v;
            g_statesh[(size_t)(b2 * 16) * SS + s] = __float2half_rn(v);
        }
    }
}

// ---------------- sum 4 split-K partials (r) ----------------
__global__ void sum4_k(const float* __restrict__ in, float* __restrict__ out) {
    const int n = BT * 1024;
    int i = (blockIdx.x * 256 + threadIdx.x) * 4;
    float4 a = *(const float4*)(in + i);
    float4 b = *(const float4*)(in + n + i);
    float4 c = *(const float4*)(in + 2 * n + i);
    float4 d = *(const float4*)(in + 3 * n + i);
    float4 o;
    o.x = a.x + b.x + c.x + d.x; o.y = a.y + b.y + c.y + d.y;
    o.z = a.z + b.z + c.z + d.z; o.w = a.w + b.w + c.w + d.w;
    *(float4*)(out + i) = o;
}

// ---------------- fused 15-step scan, software grid barrier ----------------
__global__ void __launch_bounds__(256) scan_fused_k(const float* __restrict__ Amat) {
    __shared__ float st[BB][SS];
    __shared__ float red[BB][256];
    const int tid  = threadIdx.x;
    const int col  = blockIdx.x * 16 + (tid & 15);
    const int part = tid >> 4;
    const int k0   = part * 64;

#pragma unroll 1
    for (int t = 0; t < 15; t++) {
        for (int i = tid; i < BB * SS; i += 256) {
            int b = i >> 10, s = i & 1023;
            st[b][s] = __ldcg(&g_states[(size_t)(b * 16 + t) * SS + s]);
        }
        __syncthreads();
        float acc[BB] = {};
#pragma unroll 4
        for (int k = k0; k < k0 + 64; k++) {
            float av = Amat[(size_t)k * SS + col];
#pragma unroll
            for (int b = 0; b < BB; b++) acc[b] += st[b][k] * av;
        }
#pragma unroll
        for (int b = 0; b < BB; b++) red[b][tid] = acc[b];
        __syncthreads();
        for (int o = 8; o > 0; o >>= 1) {
            if (part < o) {
#pragma unroll
                for (int b = 0; b < BB; b++) red[b][tid] += red[b][tid + (o << 4)];
            }
            __syncthreads();
        }
        if (part == 0) {
#pragma unroll
            for (int b = 0; b < BB; b++) {
                float v = red[b][tid] + g_q[(size_t)(b * 16 + t) * SS + col];
                g_states[(size_t)(b * 16 + t + 1) * SS + col] = v;
                g_statesh[(size_t)(b * 16 + t + 1) * SS + col] = __float2half_rn(v);
            }
        }
        __threadfence();
        __syncthreads();
        if (tid == 0) {
            atomicAdd(&g_barcnt, 1u);
            const unsigned target = (unsigned)((t + 1) * gridDim.x);
            while (atomicAdd(&g_barcnt, 0u) < target) {}
        }
        __syncthreads();
    }
}

// ---------------- host ----------------
extern "C" void kernel_launch(void* const* d_in, const int* in_sizes, int n_in,
                              void* d_out, int out_size) {
    const float* x     = (const float*)d_in[0];
    const float* pos   = (const float*)d_in[1];
    const float* W_in  = (const float*)d_in[2];
    const float* b_in  = (const float*)d_in[3];
    const float* W_out = (const float*)d_in[4];
    const float* b_out = (const float*)d_in[5];
    const float* Amat  = (const float*)d_in[6];
    const float* Bm    = (const float*)d_in[7];
    const float* init  = (const float*)d_in[8];
    float* out = (float*)d_out;

    __half *WoutRh, *BmRh, *ARh, *WinTRh, *BmTh, *Hth, *Gth, *MqTh, *MwTh, *Xsumh, *xbarh, *statesh;
    float *qp, *rp, *r;
    cudaGetSymbolAddress((void**)&WoutRh, g_WoutRh);
    cudaGetSymbolAddress((void**)&BmRh,   g_BmRh);
    cudaGetSymbolAddress((void**)&ARh,    g_ARh);
    cudaGetSymbolAddress((void**)&WinTRh, g_WinTRh);
    cudaGetSymbolAddress((void**)&BmTh,   g_BmTh);
    cudaGetSymbolAddress((void**)&Hth,    g_Hth);
    cudaGetSymbolAddress((void**)&Gth,    g_Gth);
    cudaGetSymbolAddress((void**)&MqTh,   g_MqTh);
    cudaGetSymbolAddress((void**)&MwTh,   g_MwTh);
    cudaGetSymbolAddress((void**)&Xsumh,  g_Xsumh);
    cudaGetSymbolAddress((void**)&xbarh,  g_xbarh);
    cudaGetSymbolAddress((void**)&statesh,g_statesh);
    cudaGetSymbolAddress((void**)&qp,     g_qp);
    cudaGetSymbolAddress((void**)&rp,     g_rp);
    cudaGetSymbolAddress((void**)&r,      g_r);

    static bool s_init = false;
    static cudaStream_t s2 = 0, s3 = 0;
    static cudaEvent_t e0, eB, eW;
    if (!s_init) {
        if (cudaStreamCreateWithFlags(&s2, cudaStreamNonBlocking) != cudaSuccess) s2 = 0;
        if (cudaStreamCreateWithFlags(&s3, cudaStreamNonBlocking) != cudaSuccess) s3 = s2;
        cudaEventCreateWithFlags(&e0, cudaEventDisableTiming);
        cudaEventCreateWithFlags(&eB, cudaEventDisableTiming);
        cudaEventCreateWithFlags(&eW, cudaEventDisableTiming);
        cudaFuncSetAttribute((const void*)f16g<0, 1>,
                             cudaFuncAttributeMaxDynamicSharedMemorySize, GEMM_SM);
        cudaFuncSetAttribute((const void*)f16g<1, 4>,
                             cudaFuncAttributeMaxDynamicSharedMemorySize, GEMM_SM);
        cudaFuncSetAttribute((const void*)f16g<2, 1>,
                             cudaFuncAttributeMaxDynamicSharedMemorySize, GEMM_SM);
        s_init = true;
    }

    // ---- fork ----
    cudaEventRecord(e0, 0);

    // s2: wprep -> bq -> batched (Ht, Gt, MqTh)  [eB]
    cudaStreamWaitEvent(s2, e0, 0);
    wprep_k<<<dim3(32, 32, 5), dim3(32, 8), 0, s2>>>(W_in, Bm, W_out, Amat);
    bq_k<<<1024, 256, 0, s2>>>(b_in);
    f16g<0, 1><<<dim3(8, 8, 3), 128, GEMM_SM, s2>>>(
        WoutRh, WoutRh, BmTh, BmRh, ARh, WinTRh, Hth, Gth, MqTh);
    cudaEventRecord(eB, s2);

    // s3: MwTh + c vector  [eW] (off the r-critical path)
    cudaStreamWaitEvent(s3, eB, 0);
    cvec_k<<<1024, 256, 0, s3>>>(b_in, b_out);
    f16g<0, 1><<<dim3(8, 8, 1), 128, GEMM_SM, s3>>>(
        Hth, nullptr, nullptr, WinTRh, nullptr, nullptr, MwTh, nullptr, nullptr);
    cudaEventRecord(eW, s3);

    // default: prepass -> xred -> q -> qinit -> scan -> r -> sum -> main
    prepass_k<<<dim3(1, BT, 8), 256>>>(x, pos);
    xred_k<<<dim3(1, BT), 256>>>();
    cudaStreamWaitEvent(0, eB, 0);
    f16g<1, 4><<<dim3(8, 1, 4), 128, GEMM_SM>>>(
        xbarh, nullptr, nullptr, MqTh, nullptr, nullptr, qp, nullptr, nullptr);
    qinit_k<<<128, 256>>>(init);
    scan_fused_k<<<64, 256>>>(Amat);
    f16g<1, 4><<<dim3(8, 1, 4), 128, GEMM_SM>>>(
        statesh, nullptr, nullptr, Gth, nullptr, nullptr, rp, nullptr, nullptr);
    sum4_k<<<128, 256>>>(rp, r);

    // main GEMM fused with r+c epilogue
    cudaStreamWaitEvent(0, eW, 0);
    f16g<2, 1><<<dim3(8, 256, 1), 128, GEMM_SM>>>(
        Xsumh, nullptr, nullptr, MwTh, nullptr, nullptr, out, nullptr, nullptr);
}